// round 1
// baseline (speedup 1.0000x reference)
#include <cuda_runtime.h>
#include <math.h>
#include <math_constants.h>

#define N_NODES 16384
#define D_IN    64
#define HEADS   5
#define C_OUT   128
#define HC      (HEADS * C_OUT)   // 640
#define KNN     16
#define NEG     0.2f

#define TM   64
#define TN   64
#define LDT  68      // padded smem stride (floats) for 64-wide tiles
#define CAP  128     // candidate buffer capacity per row
#define BSTR 129     // buffer stride (bank-conflict-free in flush)
#define TSTR 17      // top16 stride

// ---- device scratch (static: no allocations allowed) ----
__device__ float g_sq[N_NODES];
__device__ float g_xl[N_NODES * HC];
__device__ float g_xr[N_NODES * HC];
__device__ int   g_knn[N_NODES * KNN];

// ============================================================
// K1: row squared norms. warp per row.
// ============================================================
__global__ void sqnorm_kernel(const float* __restrict__ x) {
    int row  = blockIdx.x * 8 + (threadIdx.x >> 5);
    int lane = threadIdx.x & 31;
    float v0 = x[row * D_IN + lane];
    float v1 = x[row * D_IN + lane + 32];
    float s  = v0 * v0 + v1 * v1;
    #pragma unroll
    for (int o = 16; o; o >>= 1) s += __shfl_xor_sync(0xffffffffu, s, o);
    if (!lane) g_sq[row] = s;
}

// ============================================================
// K2: fused pairwise-distance SGEMM + streaming top-16 per row.
// Block = 64 rows, iterates all 16384 candidates in 64-wide tiles.
// Threshold + overflow-buffer selection; serial per-row flush.
// ============================================================
__global__ __launch_bounds__(256, 1) void knn_kernel(const float* __restrict__ x) {
    extern __shared__ float sm[];
    float* As   = sm;                       // 64*68
    float* Bs   = As + 64 * LDT;            // 64*68
    float* sqr  = Bs + 64 * LDT;            // 64
    float* sqc  = sqr + 64;                 // 64
    float* thr  = sqc + 64;                 // 64
    float* topd = thr + 64;                 // 64*17
    float* bufd = topd + 64 * TSTR;         // 64*129
    int*   topi = (int*)(bufd + 64 * BSTR); // 64*17
    int*   bufi = topi + 64 * TSTR;         // 64*129
    int*   cnt  = bufi + 64 * BSTR;         // 64

    const int tid = threadIdx.x;
    const int ty = tid >> 4, tx = tid & 15;
    const int rowbase = blockIdx.x * TM;

    // load As[k][r] = x[rowbase+r][k]  (once per block)
    {
        int r = tid >> 4;
        int d4 = (tid & 15) * 4;
        #pragma unroll
        for (int u = 0; u < 4; u++) {
            float4 v = *(const float4*)&x[(rowbase + r) * D_IN + d4];
            As[(d4 + 0) * LDT + r] = v.x;
            As[(d4 + 1) * LDT + r] = v.y;
            As[(d4 + 2) * LDT + r] = v.z;
            As[(d4 + 3) * LDT + r] = v.w;
            r += 16;
        }
    }
    if (tid < TM) {
        sqr[tid] = g_sq[rowbase + tid];
        thr[tid] = CUDART_INF_F;
        cnt[tid] = 0;
        #pragma unroll
        for (int s = 0; s < 16; s++) topd[tid * TSTR + s] = CUDART_INF_F;
    }
    __syncthreads();

    for (int colbase = 0; colbase < N_NODES; colbase += TN) {
        // stage candidate tile: Bs[k][c] = x[colbase+c][k]
        {
            int r = tid >> 4;
            int d4 = (tid & 15) * 4;
            #pragma unroll
            for (int u = 0; u < 4; u++) {
                float4 v = *(const float4*)&x[(colbase + r) * D_IN + d4];
                Bs[(d4 + 0) * LDT + r] = v.x;
                Bs[(d4 + 1) * LDT + r] = v.y;
                Bs[(d4 + 2) * LDT + r] = v.z;
                Bs[(d4 + 3) * LDT + r] = v.w;
                r += 16;
            }
        }
        if (tid < TN) sqc[tid] = g_sq[colbase + tid];
        __syncthreads();

        // 4x4 register-tiled dot products over full K=64
        float acc[4][4] = {};
        #pragma unroll
        for (int k = 0; k < D_IN; k++) {
            float4 a = *(const float4*)&As[k * LDT + ty * 4];
            float4 b = *(const float4*)&Bs[k * LDT + tx * 4];
            float av[4] = {a.x, a.y, a.z, a.w};
            float bv[4] = {b.x, b.y, b.z, b.w};
            #pragma unroll
            for (int i = 0; i < 4; i++)
                #pragma unroll
                for (int j = 0; j < 4; j++)
                    acc[i][j] += av[i] * bv[j];
        }

        // append candidates beating the row threshold
        #pragma unroll
        for (int i = 0; i < 4; i++) {
            int r  = ty * 4 + i;
            int gr = rowbase + r;
            float sr = sqr[r];
            float th = thr[r];
            #pragma unroll
            for (int j = 0; j < 4; j++) {
                int gc = colbase + tx * 4 + j;
                float d2 = sr + sqc[tx * 4 + j] - 2.0f * acc[i][j];
                if (gc != gr && d2 < th) {
                    int p = atomicAdd(&cnt[r], 1);
                    if (p < CAP) { bufd[r * BSTR + p] = d2; bufi[r * BSTR + p] = gc; }
                }
            }
        }
        __syncthreads();

        // flush rows that could overflow next tile (or final tile)
        bool last = (colbase + TN >= N_NODES);
        if (tid < TM) {
            int c = cnt[tid];
            if (c >= TN || (last && c > 0)) {
                if (c > CAP) c = CAP;
                float mx = topd[tid * TSTR]; int mp = 0;
                #pragma unroll
                for (int s = 1; s < 16; s++) {
                    float v = topd[tid * TSTR + s];
                    if (v > mx) { mx = v; mp = s; }
                }
                for (int e = 0; e < c; e++) {
                    float d = bufd[tid * BSTR + e];
                    if (d < mx) {
                        topd[tid * TSTR + mp] = d;
                        topi[tid * TSTR + mp] = bufi[tid * BSTR + e];
                        mx = topd[tid * TSTR]; mp = 0;
                        #pragma unroll
                        for (int s = 1; s < 16; s++) {
                            float v = topd[tid * TSTR + s];
                            if (v > mx) { mx = v; mp = s; }
                        }
                    }
                }
                thr[tid] = mx;
                cnt[tid] = 0;
            }
        }
        __syncthreads();
    }

    if (tid < TM) {
        #pragma unroll
        for (int s = 0; s < 16; s++)
            g_knn[(rowbase + tid) * KNN + s] = topi[tid * TSTR + s];
    }
}

// ============================================================
// K3: out = x @ W + b   ([16384,64] @ [64,640]), 64x64 tiles.
// which = 0 -> g_xl, 1 -> g_xr
// ============================================================
__global__ __launch_bounds__(256) void gemm_kernel(const float* __restrict__ x,
                                                   const float* __restrict__ W,
                                                   const float* __restrict__ b,
                                                   int which) {
    __shared__ float As[64 * LDT];
    __shared__ float Bs[64 * LDT];
    float* outp = which ? g_xr : g_xl;

    const int tid = threadIdx.x;
    const int ty = tid >> 4, tx = tid & 15;
    const int rowbase = blockIdx.x * 64;
    const int colbase = blockIdx.y * 64;

    {   // As[k][r] = x[rowbase+r][k]
        int r = tid >> 4;
        int d4 = (tid & 15) * 4;
        #pragma unroll
        for (int u = 0; u < 4; u++) {
            float4 v = *(const float4*)&x[(rowbase + r) * D_IN + d4];
            As[(d4 + 0) * LDT + r] = v.x;
            As[(d4 + 1) * LDT + r] = v.y;
            As[(d4 + 2) * LDT + r] = v.z;
            As[(d4 + 3) * LDT + r] = v.w;
            r += 16;
        }
    }
    {   // Bs[k][n] = W[k][colbase+n]
        int kk = tid >> 4;
        int n4 = (tid & 15) * 4;
        #pragma unroll
        for (int u = 0; u < 4; u++) {
            float4 v = *(const float4*)&W[kk * HC + colbase + n4];
            Bs[kk * LDT + n4 + 0] = v.x;
            Bs[kk * LDT + n4 + 1] = v.y;
            Bs[kk * LDT + n4 + 2] = v.z;
            Bs[kk * LDT + n4 + 3] = v.w;
            kk += 16;
        }
    }
    __syncthreads();

    float acc[4][4] = {};
    #pragma unroll
    for (int k = 0; k < D_IN; k++) {
        float4 a = *(const float4*)&As[k * LDT + ty * 4];
        float4 bb = *(const float4*)&Bs[k * LDT + tx * 4];
        float av[4] = {a.x, a.y, a.z, a.w};
        float bv[4] = {bb.x, bb.y, bb.z, bb.w};
        #pragma unroll
        for (int i = 0; i < 4; i++)
            #pragma unroll
            for (int j = 0; j < 4; j++)
                acc[i][j] += av[i] * bv[j];
    }

    #pragma unroll
    for (int j = 0; j < 4; j++) {
        float bj = b[colbase + tx * 4 + j];
        #pragma unroll
        for (int i = 0; i < 4; i++)
            outp[(rowbase + ty * 4 + i) * HC + colbase + tx * 4 + j] = acc[i][j] + bj;
    }
}

// ============================================================
// K4: GATv2 attention. Block per node, warp per neighbor (16 warps),
// lane covers 4 channels (float4). Warp shuffles only; shared atomics
// for the cross-neighbor sum.
// ============================================================
__global__ __launch_bounds__(512) void attn_kernel(const float* __restrict__ att,
                                                   const float* __restrict__ bias,
                                                   float* __restrict__ out) {
    __shared__ float logits[HEADS][16];
    __shared__ float alpha[HEADS][16];
    __shared__ float outsh[C_OUT];
    __shared__ int   nbr[KNN];

    const int n = blockIdx.x;
    const int tid = threadIdx.x;
    const int w = tid >> 5, lane = tid & 31;

    if (tid < KNN)  nbr[tid] = g_knn[n * KNN + tid];
    if (tid < C_OUT) outsh[tid] = 0.0f;
    __syncthreads();

    const int src = nbr[w];
    float msg[HEADS][4];

    #pragma unroll
    for (int h = 0; h < HEADS; h++) {
        float4 m  = *(const float4*)&g_xl[src * HC + h * C_OUT + lane * 4];
        float4 xr = *(const float4*)&g_xr[n   * HC + h * C_OUT + lane * 4];
        float4 a  = *(const float4*)&att[h * C_OUT + lane * 4];
        msg[h][0] = m.x; msg[h][1] = m.y; msg[h][2] = m.z; msg[h][3] = m.w;
        float e0 = m.x + xr.x; e0 = e0 > 0.f ? e0 : NEG * e0;
        float e1 = m.y + xr.y; e1 = e1 > 0.f ? e1 : NEG * e1;
        float e2 = m.z + xr.z; e2 = e2 > 0.f ? e2 : NEG * e2;
        float e3 = m.w + xr.w; e3 = e3 > 0.f ? e3 : NEG * e3;
        float p = e0 * a.x + e1 * a.y + e2 * a.z + e3 * a.w;
        #pragma unroll
        for (int o = 16; o; o >>= 1) p += __shfl_xor_sync(0xffffffffu, p, o);
        if (!lane) logits[h][w] = p;
    }
    __syncthreads();

    if (w == 0) {
        #pragma unroll
        for (int h = 0; h < HEADS; h++) {
            float v = (lane < KNN) ? logits[h][lane] : -CUDART_INF_F;
            float mx = v;
            #pragma unroll
            for (int o = 16; o; o >>= 1) mx = fmaxf(mx, __shfl_xor_sync(0xffffffffu, mx, o));
            float e = (lane < KNN) ? expf(v - mx) : 0.0f;
            float s = e;
            #pragma unroll
            for (int o = 16; o; o >>= 1) s += __shfl_xor_sync(0xffffffffu, s, o);
            if (lane < KNN) alpha[h][lane] = e / s;
        }
    }
    __syncthreads();

    float acc0 = 0.f, acc1 = 0.f, acc2 = 0.f, acc3 = 0.f;
    #pragma unroll
    for (int h = 0; h < HEADS; h++) {
        float a = alpha[h][w];
        acc0 += a * msg[h][0];
        acc1 += a * msg[h][1];
        acc2 += a * msg[h][2];
        acc3 += a * msg[h][3];
    }
    // mean over heads = * (1/5)
    atomicAdd(&outsh[lane * 4 + 0], acc0 * 0.2f);
    atomicAdd(&outsh[lane * 4 + 1], acc1 * 0.2f);
    atomicAdd(&outsh[lane * 4 + 2], acc2 * 0.2f);
    atomicAdd(&outsh[lane * 4 + 3], acc3 * 0.2f);
    __syncthreads();

    if (tid < C_OUT) out[n * C_OUT + tid] = outsh[tid] + bias[tid];
}

// ============================================================
// launch
// ============================================================
extern "C" void kernel_launch(void* const* d_in, const int* in_sizes, int n_in,
                              void* d_out, int out_size) {
    const float* x    = (const float*)d_in[0];
    const float* W_l  = (const float*)d_in[1];
    const float* b_l  = (const float*)d_in[2];
    const float* W_r  = (const float*)d_in[3];
    const float* b_r  = (const float*)d_in[4];
    const float* att  = (const float*)d_in[5];
    const float* bias = (const float*)d_in[6];
    float* out = (float*)d_out;

    // K2 dynamic smem: floats (64*68*2 + 64*3 + 64*17 + 64*129)
    //                + ints  (64*17 + 64*129 + 64)  -> 27648 elems * 4B
    const int SMEM_K2 = (64 * LDT * 2 + 64 * 3 + 64 * TSTR + 64 * BSTR
                         + 64 * TSTR + 64 * BSTR + 64) * 4;
    cudaFuncSetAttribute(knn_kernel, cudaFuncAttributeMaxDynamicSharedMemorySize, SMEM_K2);

    sqnorm_kernel<<<N_NODES / 8, 256>>>(x);
    knn_kernel<<<N_NODES / TM, 256, SMEM_K2>>>(x);
    gemm_kernel<<<dim3(N_NODES / 64, HC / 64), 256>>>(x, W_l, b_l, 0);
    gemm_kernel<<<dim3(N_NODES / 64, HC / 64), 256>>>(x, W_r, b_r, 1);
    attn_kernel<<<N_NODES, 512>>>(att, bias, out);
}

// round 3
// speedup vs baseline: 1.0741x; 1.0741x over previous
#include <cuda_runtime.h>
#include <math.h>
#include <math_constants.h>

#define N_NODES 16384
#define D_IN    64
#define HEADS   5
#define C_OUT   128
#define HC      (HEADS * C_OUT)   // 640
#define KNN     16
#define NEG     0.2f

// knn tile: 64 rows x 128 cols, 256 threads, 4x8 microtile
#define TM   64
#define TN   128
#define LDA  68      // padded smem stride for As (64-wide)
#define LDB  132     // padded smem stride for Bs (128-wide)
#define CAP  192     // candidate buffer capacity per row (start<64 + 128 inserts)
#define BSTR 193
#define TSTR 17
#define FLUSH_AT (CAP - TN)   // 64

// ---- device scratch (static: no allocations allowed) ----
__device__ float g_sq[N_NODES];
__device__ float g_xl[N_NODES * HC];
__device__ float g_xr[N_NODES * HC];
__device__ int   g_knn[N_NODES * KNN];

// ============================================================
// K1: row squared norms. warp per row.
// ============================================================
__global__ void sqnorm_kernel(const float* __restrict__ x) {
    int row  = blockIdx.x * 8 + (threadIdx.x >> 5);
    int lane = threadIdx.x & 31;
    float v0 = x[row * D_IN + lane];
    float v1 = x[row * D_IN + lane + 32];
    float s  = v0 * v0 + v1 * v1;
    #pragma unroll
    for (int o = 16; o; o >>= 1) s += __shfl_xor_sync(0xffffffffu, s, o);
    if (!lane) g_sq[row] = s;
}

// ============================================================
// K2: fused pairwise-distance SGEMM + streaming top-16 per row.
// Block = 64 rows; candidate tiles of 128 cols; 4x8 register tile.
// Threshold + overflow-buffer selection; serial per-row flush.
// ============================================================
__global__ __launch_bounds__(256, 1) void knn_kernel(const float* __restrict__ x) {
    extern __shared__ float sm[];
    float* As   = sm;                       // 64*LDA
    float* Bs   = As + 64 * LDA;            // 64*LDB
    float* sqr  = Bs + 64 * LDB;            // 64
    float* sqc  = sqr + 64;                 // 128
    float* thr  = sqc + 128;                // 64
    float* topd = thr + 64;                 // 64*17
    float* bufd = topd + 64 * TSTR;         // 64*193
    int*   topi = (int*)(bufd + 64 * BSTR); // 64*17
    int*   bufi = topi + 64 * TSTR;         // 64*193
    int*   cnt  = bufi + 64 * BSTR;         // 64

    const int tid = threadIdx.x;
    const int ty = tid >> 4, tx = tid & 15;   // 16x16 thread grid
    const int rowbase = blockIdx.x * TM;

    // load As[k][r] = x[rowbase+r][k]  (once per block)
    {
        int r = tid >> 4;
        int d4 = (tid & 15) * 4;
        #pragma unroll
        for (int u = 0; u < 4; u++) {
            float4 v = *(const float4*)&x[(rowbase + r) * D_IN + d4];
            As[(d4 + 0) * LDA + r] = v.x;
            As[(d4 + 1) * LDA + r] = v.y;
            As[(d4 + 2) * LDA + r] = v.z;
            As[(d4 + 3) * LDA + r] = v.w;
            r += 16;
        }
    }
    if (tid < TM) {
        sqr[tid] = g_sq[rowbase + tid];
        thr[tid] = CUDART_INF_F;
        cnt[tid] = 0;
        #pragma unroll
        for (int s = 0; s < 16; s++) topd[tid * TSTR + s] = CUDART_INF_F;
    }
    __syncthreads();

    for (int colbase = 0; colbase < N_NODES; colbase += TN) {
        // stage candidate tile: Bs[k][c] = x[colbase+c][k]  (128 rows x 64)
        {
            int r = tid >> 4;
            int d4 = (tid & 15) * 4;
            #pragma unroll
            for (int u = 0; u < 8; u++) {
                float4 v = *(const float4*)&x[(colbase + r) * D_IN + d4];
                Bs[(d4 + 0) * LDB + r] = v.x;
                Bs[(d4 + 1) * LDB + r] = v.y;
                Bs[(d4 + 2) * LDB + r] = v.z;
                Bs[(d4 + 3) * LDB + r] = v.w;
                r += 16;
            }
        }
        if (tid < TN) sqc[tid] = g_sq[colbase + tid];
        __syncthreads();

        // 4x8 register-tiled dot products over full K=64
        float acc[4][8] = {};
        #pragma unroll
        for (int k = 0; k < D_IN; k++) {
            float4 a  = *(const float4*)&As[k * LDA + ty * 4];
            float4 b0 = *(const float4*)&Bs[k * LDB + tx * 8];
            float4 b1 = *(const float4*)&Bs[k * LDB + tx * 8 + 4];
            float av[4] = {a.x, a.y, a.z, a.w};
            float bv[8] = {b0.x, b0.y, b0.z, b0.w, b1.x, b1.y, b1.z, b1.w};
            #pragma unroll
            for (int i = 0; i < 4; i++)
                #pragma unroll
                for (int j = 0; j < 8; j++)
                    acc[i][j] += av[i] * bv[j];
        }

        // append candidates beating the row threshold
        #pragma unroll
        for (int i = 0; i < 4; i++) {
            int r  = ty * 4 + i;
            int gr = rowbase + r;
            float sr = sqr[r];
            float th = thr[r];
            #pragma unroll
            for (int j = 0; j < 8; j++) {
                int gc = colbase + tx * 8 + j;
                float d2 = sr + sqc[tx * 8 + j] - 2.0f * acc[i][j];
                if (gc != gr && d2 < th) {
                    int p = atomicAdd(&cnt[r], 1);
                    if (p < CAP) { bufd[r * BSTR + p] = d2; bufi[r * BSTR + p] = gc; }
                }
            }
        }
        __syncthreads();

        // flush rows that could overflow next tile (or final tile)
        bool last = (colbase + TN >= N_NODES);
        if (tid < TM) {
            int c = cnt[tid];
            if (c >= FLUSH_AT || (last && c > 0)) {
                if (c > CAP) c = CAP;
                float mx = topd[tid * TSTR]; int mp = 0;
                #pragma unroll
                for (int s = 1; s < 16; s++) {
                    float v = topd[tid * TSTR + s];
                    if (v > mx) { mx = v; mp = s; }
                }
                for (int e = 0; e < c; e++) {
                    float d = bufd[tid * BSTR + e];
                    if (d < mx) {
                        topd[tid * TSTR + mp] = d;
                        topi[tid * TSTR + mp] = bufi[tid * BSTR + e];
                        mx = topd[tid * TSTR]; mp = 0;
                        #pragma unroll
                        for (int s = 1; s < 16; s++) {
                            float v = topd[tid * TSTR + s];
                            if (v > mx) { mx = v; mp = s; }
                        }
                    }
                }
                thr[tid] = mx;
                cnt[tid] = 0;
            }
        }
        __syncthreads();
    }

    if (tid < TM) {
        #pragma unroll
        for (int s = 0; s < 16; s++)
            g_knn[(rowbase + tid) * KNN + s] = topi[tid * TSTR + s];
    }
}

// ============================================================
// K3: out = x @ W + b   ([16384,64] @ [64,640]), 64x128 tiles,
// 4x8 microtile, dynamic smem. which = 0 -> g_xl, 1 -> g_xr
// ============================================================
__global__ __launch_bounds__(256) void gemm_kernel(const float* __restrict__ x,
                                                   const float* __restrict__ W,
                                                   const float* __restrict__ b,
                                                   int which) {
    extern __shared__ float smg[];
    float* As = smg;               // 64*LDA
    float* Bs = As + 64 * LDA;     // 64*LDB
    float* outp = which ? g_xr : g_xl;

    const int tid = threadIdx.x;
    const int ty = tid >> 4, tx = tid & 15;
    const int rowbase = blockIdx.x * 64;
    const int colbase = blockIdx.y * 128;

    {   // As[k][r] = x[rowbase+r][k]
        int r = tid >> 4;
        int d4 = (tid & 15) * 4;
        #pragma unroll
        for (int u = 0; u < 4; u++) {
            float4 v = *(const float4*)&x[(rowbase + r) * D_IN + d4];
            As[(d4 + 0) * LDA + r] = v.x;
            As[(d4 + 1) * LDA + r] = v.y;
            As[(d4 + 2) * LDA + r] = v.z;
            As[(d4 + 3) * LDA + r] = v.w;
            r += 16;
        }
    }
    {   // Bs[k][n] = W[k][colbase+n]  (64 x 128)
        #pragma unroll
        for (int u = 0; u < 8; u++) {
            int l  = tid * 8 + u;          // 0..2047 float4 slots
            int kk = l >> 5;               // 0..63
            int n4 = (l & 31) * 4;         // 0..124
            float4 v = *(const float4*)&W[kk * HC + colbase + n4];
            Bs[kk * LDB + n4 + 0] = v.x;
            Bs[kk * LDB + n4 + 1] = v.y;
            Bs[kk * LDB + n4 + 2] = v.z;
            Bs[kk * LDB + n4 + 3] = v.w;
        }
    }
    __syncthreads();

    float acc[4][8] = {};
    #pragma unroll
    for (int k = 0; k < D_IN; k++) {
        float4 a  = *(const float4*)&As[k * LDA + ty * 4];
        float4 b0 = *(const float4*)&Bs[k * LDB + tx * 8];
        float4 b1 = *(const float4*)&Bs[k * LDB + tx * 8 + 4];
        float av[4] = {a.x, a.y, a.z, a.w};
        float bv[8] = {b0.x, b0.y, b0.z, b0.w, b1.x, b1.y, b1.z, b1.w};
        #pragma unroll
        for (int i = 0; i < 4; i++)
            #pragma unroll
            for (int j = 0; j < 8; j++)
                acc[i][j] += av[i] * bv[j];
    }

    #pragma unroll
    for (int j = 0; j < 8; j++) {
        float bj = b[colbase + tx * 8 + j];
        #pragma unroll
        for (int i = 0; i < 4; i++)
            outp[(rowbase + ty * 4 + i) * HC + colbase + tx * 8 + j] = acc[i][j] + bj;
    }
}

// ============================================================
// K4: GATv2 attention. Block per node, warp per neighbor (16 warps),
// lane covers 4 channels (float4). Warp shuffles only; shared atomics
// for the cross-neighbor sum.
// ============================================================
__global__ __launch_bounds__(512) void attn_kernel(const float* __restrict__ att,
                                                   const float* __restrict__ bias,
                                                   float* __restrict__ out) {
    __shared__ float logits[HEADS][16];
    __shared__ float alpha[HEADS][16];
    __shared__ float outsh[C_OUT];
    __shared__ int   nbr[KNN];

    const int n = blockIdx.x;
    const int tid = threadIdx.x;
    const int w = tid >> 5, lane = tid & 31;

    if (tid < KNN)  nbr[tid] = g_knn[n * KNN + tid];
    if (tid < C_OUT) outsh[tid] = 0.0f;
    __syncthreads();

    const int src = nbr[w];
    float msg[HEADS][4];

    #pragma unroll
    for (int h = 0; h < HEADS; h++) {
        float4 m  = *(const float4*)&g_xl[src * HC + h * C_OUT + lane * 4];
        float4 xr = *(const float4*)&g_xr[n   * HC + h * C_OUT + lane * 4];
        float4 a  = *(const float4*)&att[h * C_OUT + lane * 4];
        msg[h][0] = m.x; msg[h][1] = m.y; msg[h][2] = m.z; msg[h][3] = m.w;
        float e0 = m.x + xr.x; e0 = e0 > 0.f ? e0 : NEG * e0;
        float e1 = m.y + xr.y; e1 = e1 > 0.f ? e1 : NEG * e1;
        float e2 = m.z + xr.z; e2 = e2 > 0.f ? e2 : NEG * e2;
        float e3 = m.w + xr.w; e3 = e3 > 0.f ? e3 : NEG * e3;
        float p = e0 * a.x + e1 * a.y + e2 * a.z + e3 * a.w;
        #pragma unroll
        for (int o = 16; o; o >>= 1) p += __shfl_xor_sync(0xffffffffu, p, o);
        if (!lane) logits[h][w] = p;
    }
    __syncthreads();

    if (w == 0) {
        #pragma unroll
        for (int h = 0; h < HEADS; h++) {
            float v = (lane < KNN) ? logits[h][lane] : -CUDART_INF_F;
            float mx = v;
            #pragma unroll
            for (int o = 16; o; o >>= 1) mx = fmaxf(mx, __shfl_xor_sync(0xffffffffu, mx, o));
            float e = (lane < KNN) ? expf(v - mx) : 0.0f;
            float s = e;
            #pragma unroll
            for (int o = 16; o; o >>= 1) s += __shfl_xor_sync(0xffffffffu, s, o);
            if (lane < KNN) alpha[h][lane] = e / s;
        }
    }
    __syncthreads();

    float acc0 = 0.f, acc1 = 0.f, acc2 = 0.f, acc3 = 0.f;
    #pragma unroll
    for (int h = 0; h < HEADS; h++) {
        float a = alpha[h][w];
        acc0 += a * msg[h][0];
        acc1 += a * msg[h][1];
        acc2 += a * msg[h][2];
        acc3 += a * msg[h][3];
    }
    // mean over heads = * (1/5)
    atomicAdd(&outsh[lane * 4 + 0], acc0 * 0.2f);
    atomicAdd(&outsh[lane * 4 + 1], acc1 * 0.2f);
    atomicAdd(&outsh[lane * 4 + 2], acc2 * 0.2f);
    atomicAdd(&outsh[lane * 4 + 3], acc3 * 0.2f);
    __syncthreads();

    if (tid < C_OUT) out[n * C_OUT + tid] = outsh[tid] + bias[tid];
}

// ============================================================
// launch
// ============================================================
extern "C" void kernel_launch(void* const* d_in, const int* in_sizes, int n_in,
                              void* d_out, int out_size) {
    const float* x    = (const float*)d_in[0];
    const float* W_l  = (const float*)d_in[1];
    const float* b_l  = (const float*)d_in[2];
    const float* W_r  = (const float*)d_in[3];
    const float* b_r  = (const float*)d_in[4];
    const float* att  = (const float*)d_in[5];
    const float* bias = (const float*)d_in[6];
    float* out = (float*)d_out;

    const int SMEM_K2 = (64 * LDA + 64 * LDB + 64 + 128 + 64
                         + 64 * TSTR + 64 * BSTR
                         + 64 * TSTR + 64 * BSTR + 64) * 4;
    const int SMEM_G  = (64 * LDA + 64 * LDB) * 4;   // 51200 B
    cudaFuncSetAttribute(knn_kernel, cudaFuncAttributeMaxDynamicSharedMemorySize, SMEM_K2);
    cudaFuncSetAttribute(gemm_kernel, cudaFuncAttributeMaxDynamicSharedMemorySize, SMEM_G);

    sqnorm_kernel<<<N_NODES / 8, 256>>>(x);
    knn_kernel<<<N_NODES / TM, 256, SMEM_K2>>>(x);
    gemm_kernel<<<dim3(N_NODES / 64, HC / 128), 256, SMEM_G>>>(x, W_l, b_l, 0);
    gemm_kernel<<<dim3(N_NODES / 64, HC / 128), 256, SMEM_G>>>(x, W_r, b_r, 1);
    attn_kernel<<<N_NODES, 512>>>(att, bias, out);
}